// round 9
// baseline (speedup 1.0000x reference)
#include <cuda_runtime.h>

#define BB   256
#define TT   2048
#define INP  29
#define HH   64
#define GG   192   // 3*H
#define NN2  384   // both directions
#define OUTD 11
#define MT   ((size_t)BB * TT)

// Scratch (device globals — no allocation allowed)
__device__ float g_out0[(size_t)BB * TT * 2 * HH];   // [B*T][128] layer-0 bi output
__device__ float g_gx0[(size_t)BB * TT * NN2];       // [B*T][384] layer-0 input gates
__device__ float g_gx1[(size_t)BB * TT * NN2];       // [B*T][384] layer-1 input gates
__device__ float g_hT[BB * 2 * HH];                  // [B][128] final states of layer 1
__device__ float g_Wt0[32 * NN2];                    // transposed layer-0 Wih (padded K=32)
__device__ float g_Wt1[128 * NN2];                   // transposed layer-1 Wih

// ---------------------------------------------------------------------------
// f32x2 packed helpers (Blackwell FFMA2 — 2x fp32 FMA throughput)
// ---------------------------------------------------------------------------
__device__ __forceinline__ void fma2(unsigned long long& acc,
                                     unsigned long long a, unsigned long long b) {
    asm("fma.rn.f32x2 %0, %1, %2, %0;" : "+l"(acc) : "l"(a), "l"(b));
}
__device__ __forceinline__ unsigned long long dup2(float f) {
    unsigned long long d;
    unsigned int u = __float_as_uint(f);
    asm("mov.b64 %0, {%1, %1};" : "=l"(d) : "r"(u));
    return d;
}
__device__ __forceinline__ float2 unpk(unsigned long long v) {
    unsigned int a, b;
    asm("mov.b64 {%0, %1}, %2;" : "=r"(a), "=r"(b) : "l"(v));
    float2 r; r.x = __uint_as_float(a); r.y = __uint_as_float(b);
    return r;
}

// Clamp-free fast activations (safe at +/-inf by construction).
__device__ __forceinline__ float sigf(float v) {
    float e = __expf(-v);
    return __fdividef(1.f, 1.f + e);
}
__device__ __forceinline__ float tanh_f(float v) {
    float e = __expf(-2.f * v);
    return __fdividef(2.f, 1.f + e) - 1.f;
}

// ---------------------------------------------------------------------------
// One-time W transpose: Wt[k][384] (zero-padded in k), coalesced writes.
// ---------------------------------------------------------------------------
__global__ void transpose_w_kernel(const float* __restrict__ Wf,
                                   const float* __restrict__ Wb,
                                   float* __restrict__ Wt,
                                   int K, int KREAL)
{
    int idx = blockIdx.x * 256 + threadIdx.x;
    if (idx >= K * NN2) return;
    int n = idx % NN2, k = idx / NN2;
    const float* W = (n < GG) ? Wf : Wb;
    int nn = (n < GG) ? n : n - GG;
    Wt[(size_t)k * NN2 + n] = (k < KREAL) ? W[nn * KREAL + k] : 0.f;
}

// ---------------------------------------------------------------------------
// Input-gate GEMM (R7, measured good): gx[m][384] = A[m][K]@Wt + b
// CTA tile: 128 M x 64 N, 256 threads, thread tile 8M x 4N via f32x2 M-pairs.
// grid = (6 n-tiles, m-tiles): n-tiles launch-adjacent -> A tile L2-resident.
// ---------------------------------------------------------------------------
template<int KK, int KREAL>
__global__ void __launch_bounds__(256, 2) gemm_gx_kernel(
    const float* __restrict__ A, int lda,
    const float* __restrict__ Wt,
    const float* __restrict__ bf, const float* __restrict__ bb,
    float* __restrict__ gx)
{
    extern __shared__ float sm[];
    float* xT = sm;               // [KK][128]
    float* ws = sm + KK * 128;    // [KK][64]

    const int tid = threadIdx.x;
    const int n0g = blockIdx.x * 64;
    const int m0g = blockIdx.y * 128;

    if (KK == KREAL) {
#pragma unroll
        for (int it = 0; it < 128 * (KK / 4) / 256; it++) {
            int idx = tid + it * 256;
            int m = idx % 128, k4 = idx / 128;
            float4 v = *(const float4*)&A[(size_t)(m0g + m) * lda + k4 * 4];
            xT[(k4 * 4 + 0) * 128 + m] = v.x;
            xT[(k4 * 4 + 1) * 128 + m] = v.y;
            xT[(k4 * 4 + 2) * 128 + m] = v.z;
            xT[(k4 * 4 + 3) * 128 + m] = v.w;
        }
    } else {
#pragma unroll
        for (int it = 0; it < 128 * KK / 256; it++) {
            int idx = tid + it * 256;
            int m = idx % 128, k = idx / 128;
            xT[k * 128 + m] = (k < KREAL) ? A[(size_t)(m0g + m) * lda + k] : 0.f;
        }
    }
#pragma unroll
    for (int it = 0; it < KK * 16 / 256; it++) {
        int idx = tid + it * 256;
        int n4 = idx % 16, k = idx / 16;
        *(float4*)&ws[k * 64 + n4 * 4] =
            *(const float4*)&Wt[(size_t)k * NN2 + n0g + n4 * 4];
    }
    __syncthreads();

    const int ty = tid / 16, tx = tid % 16;
    const int m0 = ty * 8, n0 = tx * 4;

    unsigned long long acc[4][4];
#pragma unroll
    for (int j = 0; j < 4; j++)
#pragma unroll
        for (int p = 0; p < 4; p++) acc[j][p] = 0ull;

#pragma unroll 4
    for (int k = 0; k < KK; k++) {
        ulonglong2 xa = *(const ulonglong2*)&xT[k * 128 + m0];
        ulonglong2 xb = *(const ulonglong2*)&xT[k * 128 + m0 + 4];
        float4 wv = *(const float4*)&ws[k * 64 + n0];
        unsigned long long w0 = dup2(wv.x), w1 = dup2(wv.y),
                           w2 = dup2(wv.z), w3 = dup2(wv.w);
        fma2(acc[0][0], w0, xa.x); fma2(acc[0][1], w0, xa.y);
        fma2(acc[0][2], w0, xb.x); fma2(acc[0][3], w0, xb.y);
        fma2(acc[1][0], w1, xa.x); fma2(acc[1][1], w1, xa.y);
        fma2(acc[1][2], w1, xb.x); fma2(acc[1][3], w1, xb.y);
        fma2(acc[2][0], w2, xa.x); fma2(acc[2][1], w2, xa.y);
        fma2(acc[2][2], w2, xb.x); fma2(acc[2][3], w2, xb.y);
        fma2(acc[3][0], w3, xa.x); fma2(acc[3][1], w3, xa.y);
        fma2(acc[3][2], w3, xb.x); fma2(acc[3][3], w3, xb.y);
    }

    float bias[4];
#pragma unroll
    for (int j = 0; j < 4; j++) {
        int ng = n0g + n0 + j;
        bias[j] = (ng < GG) ? bf[ng] : bb[ng - GG];
    }
    float2 u[4][4];
#pragma unroll
    for (int j = 0; j < 4; j++)
#pragma unroll
        for (int p = 0; p < 4; p++) u[j][p] = unpk(acc[j][p]);

#pragma unroll
    for (int i = 0; i < 8; i++) {
        int p = i >> 1, h = i & 1;
        float4 o;
        o.x = (h ? u[0][p].y : u[0][p].x) + bias[0];
        o.y = (h ? u[1][p].y : u[1][p].x) + bias[1];
        o.z = (h ? u[2][p].y : u[2][p].x) + bias[2];
        o.w = (h ? u[3][p].y : u[3][p].x) + bias[3];
        size_t m = (size_t)(m0g + m0 + i);
        *(float4*)&gx[m * NN2 + n0g + n0] = o;
    }
}

// ---------------------------------------------------------------------------
// Recurrence v7: fully thread-local gate dots, ONE barrier per step.
//   128 threads, thread (r = tid/64, k = tid%64) owns output element (r,k):
//   computes all 3 gate dots with c-pair f32x2 SIMD (wr/wz/wn: 96 u64 regs).
//   One 16B broadcast LDS feeds 6 FFMA2. h double-buffered in smem.
//   grid = 256 CTAs, 2 CTAs/SM (cross-CTA overlap fills MUFU/barrier tail).
// ---------------------------------------------------------------------------
#define RRC 2
__global__ void __launch_bounds__(128, 2) rec_kernel(
    const float* __restrict__ gx,   // [B*T][384], this dir at +dir*192
    const float* __restrict__ Whh_f, const float* __restrict__ bhh_f,
    const float* __restrict__ Whh_b, const float* __restrict__ bhh_b,
    float* __restrict__ out_seq,    // g_out0 or nullptr
    float* __restrict__ hT)         // g_hT or nullptr
{
    const int dir = blockIdx.y;
    const int b0  = blockIdx.x * RRC;
    const int tid = threadIdx.x;
    const int r   = tid >> 6;       // batch row within CTA
    const int k   = tid & 63;       // hidden unit

    const float* Whh = dir ? Whh_b : Whh_f;
    const float* bhh = dir ? bhh_b : bhh_f;

    // c-pair packed weights for this thread's 3 gate rows (k, 64+k, 128+k)
    unsigned long long wr[32], wz[32], wn[32];
#pragma unroll
    for (int i = 0; i < 32; i++) {
        wr[i] = *(const unsigned long long*)&Whh[(k)        * HH + 2 * i];
        wz[i] = *(const unsigned long long*)&Whh[(64 + k)   * HH + 2 * i];
        wn[i] = *(const unsigned long long*)&Whh[(128 + k)  * HH + 2 * i];
    }
    const float bhr = bhh[k], bhz = bhh[64 + k], bhn = bhh[128 + k];

    __shared__ __align__(16) float h_sm[2][RRC][HH];   // double-buffered state
    __shared__ __align__(16) float x_sm[2][RRC][GG];

    h_sm[0][r][k] = 0.f;
    float h_reg = 0.f;

    const int tstep = dir ? -1 : 1;
    int t = dir ? (TT - 1) : 0;

    // prefetch lanes: 2*192 = 384 gx floats/step, 96 threads x LDG.128
    const bool pf_lane = (tid < 96);
    const int pr = tid / 48, pg = (tid % 48) * 4;
    const size_t pbase = ((size_t)(b0 + pr) * TT) * NN2 + (size_t)dir * GG + pg;

    float4 pf_next = make_float4(0.f, 0.f, 0.f, 0.f);
    if (pf_lane) {
        *(float4*)&x_sm[0][pr][pg] = *(const float4*)&gx[pbase + (size_t)t * NN2];
        if (TT > 1)
            pf_next = *(const float4*)&gx[pbase + (size_t)(t + tstep) * NN2];
    }
    __syncthreads();

    for (int s = 0; s < TT; s++, t += tstep) {
        const int cur = s & 1;

        // issue LDG for step s+2 now (consumed at step s+1's store)
        float4 pf_next2 = make_float4(0.f, 0.f, 0.f, 0.f);
        if (pf_lane && s + 2 < TT)
            pf_next2 = *(const float4*)&gx[pbase + (size_t)(t + 2 * tstep) * NN2];

        // three gate dots, c-pair SIMD; 6 accumulator chains (16 deep each)
        const float* hrow = &h_sm[cur][r][0];
        unsigned long long ar0 = 0ull, ar1 = 0ull;
        unsigned long long az0 = 0ull, az1 = 0ull;
        unsigned long long an0 = 0ull, an1 = 0ull;
#pragma unroll
        for (int i = 0; i < 16; i++) {
            ulonglong2 hp = *(const ulonglong2*)&hrow[i * 4];
            fma2(ar0, wr[2 * i],     hp.x);
            fma2(az0, wz[2 * i],     hp.x);
            fma2(an0, wn[2 * i],     hp.x);
            fma2(ar1, wr[2 * i + 1], hp.y);
            fma2(az1, wz[2 * i + 1], hp.y);
            fma2(an1, wn[2 * i + 1], hp.y);
        }
        float2 u0, u1;
        u0 = unpk(ar0); u1 = unpk(ar1);
        float hr = (u0.x + u0.y) + (u1.x + u1.y) + bhr;
        u0 = unpk(az0); u1 = unpk(az1);
        float hz = (u0.x + u0.y) + (u1.x + u1.y) + bhz;
        u0 = unpk(an0); u1 = unpk(an1);
        float hn = (u0.x + u0.y) + (u1.x + u1.y) + bhn;

        float xr = x_sm[cur][r][k];
        float xz = x_sm[cur][r][64 + k];
        float xn = x_sm[cur][r][128 + k];

        float rg = sigf(xr + hr);
        float zg = sigf(xz + hz);
        float ng = tanh_f(xn + rg * hn);
        h_reg = (1.f - zg) * ng + zg * h_reg;
        h_sm[cur ^ 1][r][k] = h_reg;          // write OTHER buffer: no read race

        if (pf_lane && s + 1 < TT) *(float4*)&x_sm[cur ^ 1][pr][pg] = pf_next;
        pf_next = pf_next2;

        if (out_seq)
            out_seq[((size_t)(b0 + r) * TT + t) * 128 + dir * HH + k] = h_reg;

        __syncthreads();                       // ONE barrier per step
    }

    if (hT)
        hT[(b0 + r) * 128 + dir * HH + k] = h_reg;
}

// ---------------------------------------------------------------------------
// Head: LayerNorm(128) -> Linear(128->64)+ReLU -> Linear(64->11)
// ---------------------------------------------------------------------------
__global__ void __launch_bounds__(128, 4) head_kernel(
    const float* __restrict__ ln_g, const float* __restrict__ ln_b,
    const float* __restrict__ W1, const float* __restrict__ b1,
    const float* __restrict__ W2, const float* __restrict__ b2,
    float* __restrict__ out)
{
    const int b = blockIdx.x;
    const int tid = threadIdx.x;
    const int lane = tid & 31, wid = tid >> 5;

    __shared__ float y_sm[128];
    __shared__ float h_sm[HH];
    __shared__ float r1[4], r2[4];
    __shared__ float stats[2];

    float e = g_hT[b * 128 + tid];
    float s1 = e, s2 = e * e;
#pragma unroll
    for (int o = 16; o; o >>= 1) {
        s1 += __shfl_down_sync(0xffffffffu, s1, o);
        s2 += __shfl_down_sync(0xffffffffu, s2, o);
    }
    if (lane == 0) { r1[wid] = s1; r2[wid] = s2; }
    __syncthreads();
    if (tid == 0) {
        float a = r1[0] + r1[1] + r1[2] + r1[3];
        float c = r2[0] + r2[1] + r2[2] + r2[3];
        float mu = a * (1.f / 128.f);
        float var = c * (1.f / 128.f) - mu * mu;
        stats[0] = mu;
        stats[1] = rsqrtf(var + 1e-5f);
    }
    __syncthreads();
    y_sm[tid] = (e - stats[0]) * stats[1] * ln_g[tid] + ln_b[tid];
    __syncthreads();

    if (tid < HH) {
        float acc = b1[tid];
#pragma unroll
        for (int kk = 0; kk < 128; kk++) acc += W1[tid * 128 + kk] * y_sm[kk];
        h_sm[tid] = fmaxf(acc, 0.f);
    }
    __syncthreads();
    if (tid < OUTD) {
        float acc = b2[tid];
#pragma unroll
        for (int kk = 0; kk < HH; kk++) acc += W2[tid * HH + kk] * h_sm[kk];
        out[b * OUTD + tid] = acc;
    }
}

// ---------------------------------------------------------------------------
extern "C" void kernel_launch(void* const* d_in, const int* in_sizes, int n_in,
                              void* d_out, int out_size) {
    (void)in_sizes; (void)n_in; (void)out_size;
    const float* x     = (const float*)d_in[0];
    const float* Wih00 = (const float*)d_in[1];
    const float* Whh00 = (const float*)d_in[2];
    const float* bih00 = (const float*)d_in[3];
    const float* bhh00 = (const float*)d_in[4];
    const float* Wih01 = (const float*)d_in[5];
    const float* Whh01 = (const float*)d_in[6];
    const float* bih01 = (const float*)d_in[7];
    const float* bhh01 = (const float*)d_in[8];
    const float* Wih10 = (const float*)d_in[9];
    const float* Whh10 = (const float*)d_in[10];
    const float* bih10 = (const float*)d_in[11];
    const float* bhh10 = (const float*)d_in[12];
    const float* Wih11 = (const float*)d_in[13];
    const float* Whh11 = (const float*)d_in[14];
    const float* bih11 = (const float*)d_in[15];
    const float* bhh11 = (const float*)d_in[16];
    const float* ln_g  = (const float*)d_in[17];
    const float* ln_b  = (const float*)d_in[18];
    const float* W1    = (const float*)d_in[19];
    const float* b1    = (const float*)d_in[20];
    const float* W2    = (const float*)d_in[21];
    const float* b2    = (const float*)d_in[22];
    float* out = (float*)d_out;

    float* gx0  = nullptr; cudaGetSymbolAddress((void**)&gx0,  g_gx0);
    float* gx1  = nullptr; cudaGetSymbolAddress((void**)&gx1,  g_gx1);
    float* out0 = nullptr; cudaGetSymbolAddress((void**)&out0, g_out0);
    float* hT   = nullptr; cudaGetSymbolAddress((void**)&hT,   g_hT);
    float* Wt0  = nullptr; cudaGetSymbolAddress((void**)&Wt0,  g_Wt0);
    float* Wt1  = nullptr; cudaGetSymbolAddress((void**)&Wt1,  g_Wt1);

    const int smem32  = (32 * 128 + 32 * 64) * 4;
    const int smem128 = (128 * 128 + 128 * 64) * 4;
    cudaFuncSetAttribute(gemm_gx_kernel<32, 29>,
                         cudaFuncAttributeMaxDynamicSharedMemorySize, smem32);
    cudaFuncSetAttribute(gemm_gx_kernel<128, 128>,
                         cudaFuncAttributeMaxDynamicSharedMemorySize, smem128);

    // one-time weight transposes (tiny)
    transpose_w_kernel<<<(32 * NN2 + 255) / 256, 256>>>(Wih00, Wih01, Wt0, 32, INP);
    transpose_w_kernel<<<(128 * NN2 + 255) / 256, 256>>>(Wih10, Wih11, Wt1, 128, 128);

    dim3 ggrid(6, MT / 128);      // n-tiles fastest -> A tile read ~once from DRAM
    dim3 rgrid(BB / RRC, 2);      // 256 CTAs -> 2 CTAs/SM

    gemm_gx_kernel<32, 29><<<ggrid, 256, smem32>>>(x, INP, Wt0, bih00, bih01, gx0);
    rec_kernel<<<rgrid, 128>>>(gx0, Whh00, bhh00, Whh01, bhh01, out0, nullptr);
    gemm_gx_kernel<128, 128><<<ggrid, 256, smem128>>>(out0, 128, Wt1, bih10, bih11, gx1);
    rec_kernel<<<rgrid, 128>>>(gx1, Whh10, bhh10, Whh11, bhh11, nullptr, hT);
    head_kernel<<<BB, 128>>>(ln_g, ln_b, W1, b1, W2, b2, out);
}

// round 10
// speedup vs baseline: 1.1302x; 1.1302x over previous
#include <cuda_runtime.h>

#define BB   256
#define TT   2048
#define INP  29
#define HH   64
#define GG   192   // 3*H
#define NN2  384   // both directions
#define OUTD 11
#define MT   ((size_t)BB * TT)

// Scratch (device globals — no allocation allowed)
__device__ float g_out0[(size_t)BB * TT * 2 * HH];   // [B*T][128] layer-0 bi output
__device__ float g_gx0[(size_t)BB * TT * NN2];       // [B*T][384] layer-0 input gates
__device__ float g_gx1[(size_t)BB * TT * NN2];       // [B*T][384] layer-1 input gates
__device__ float g_hT[BB * 2 * HH];                  // [B][128] final states of layer 1
__device__ float g_Wt0[32 * NN2];                    // transposed layer-0 Wih (padded K=32)
__device__ float g_Wt1[128 * NN2];                   // transposed layer-1 Wih

// ---------------------------------------------------------------------------
// f32x2 packed helpers (Blackwell FFMA2 — 2x fp32 FMA throughput)
// ---------------------------------------------------------------------------
__device__ __forceinline__ void fma2(unsigned long long& acc,
                                     unsigned long long a, unsigned long long b) {
    asm("fma.rn.f32x2 %0, %1, %2, %0;" : "+l"(acc) : "l"(a), "l"(b));
}
__device__ __forceinline__ unsigned long long dup2(float f) {
    unsigned long long d;
    unsigned int u = __float_as_uint(f);
    asm("mov.b64 %0, {%1, %1};" : "=l"(d) : "r"(u));
    return d;
}
__device__ __forceinline__ unsigned long long pack2(float lo, float hi) {
    unsigned long long d;
    asm("mov.b64 %0, {%1, %2};" : "=l"(d)
        : "r"(__float_as_uint(lo)), "r"(__float_as_uint(hi)));
    return d;
}
__device__ __forceinline__ float2 unpk(unsigned long long v) {
    unsigned int a, b;
    asm("mov.b64 {%0, %1}, %2;" : "=r"(a), "=r"(b) : "l"(v));
    float2 r; r.x = __uint_as_float(a); r.y = __uint_as_float(b);
    return r;
}

// Clamp-free fast activations (safe at +/-inf by construction).
__device__ __forceinline__ float sigf(float v) {
    float e = __expf(-v);
    return __fdividef(1.f, 1.f + e);
}
__device__ __forceinline__ float tanh_f(float v) {
    float e = __expf(-2.f * v);
    return __fdividef(2.f, 1.f + e) - 1.f;
}

// ---------------------------------------------------------------------------
// One-time W transpose: Wt[k][384] (zero-padded in k), coalesced writes.
// ---------------------------------------------------------------------------
__global__ void transpose_w_kernel(const float* __restrict__ Wf,
                                   const float* __restrict__ Wb,
                                   float* __restrict__ Wt,
                                   int K, int KREAL)
{
    int idx = blockIdx.x * 256 + threadIdx.x;
    if (idx >= K * NN2) return;
    int n = idx % NN2, k = idx / NN2;
    const float* W = (n < GG) ? Wf : Wb;
    int nn = (n < GG) ? n : n - GG;
    Wt[(size_t)k * NN2 + n] = (k < KREAL) ? W[nn * KREAL + k] : 0.f;
}

// ---------------------------------------------------------------------------
// Input-gate GEMM (R7, measured good): gx[m][384] = A[m][K]@Wt + b
// CTA tile: 128 M x 64 N, 256 threads, thread tile 8M x 4N via f32x2 M-pairs.
// grid = (6 n-tiles, m-tiles): n-tiles launch-adjacent -> A tile L2-resident.
// ---------------------------------------------------------------------------
template<int KK, int KREAL>
__global__ void __launch_bounds__(256, 2) gemm_gx_kernel(
    const float* __restrict__ A, int lda,
    const float* __restrict__ Wt,
    const float* __restrict__ bf, const float* __restrict__ bb,
    float* __restrict__ gx)
{
    extern __shared__ float sm[];
    float* xT = sm;               // [KK][128]
    float* ws = sm + KK * 128;    // [KK][64]

    const int tid = threadIdx.x;
    const int n0g = blockIdx.x * 64;
    const int m0g = blockIdx.y * 128;

    if (KK == KREAL) {
#pragma unroll
        for (int it = 0; it < 128 * (KK / 4) / 256; it++) {
            int idx = tid + it * 256;
            int m = idx % 128, k4 = idx / 128;
            float4 v = *(const float4*)&A[(size_t)(m0g + m) * lda + k4 * 4];
            xT[(k4 * 4 + 0) * 128 + m] = v.x;
            xT[(k4 * 4 + 1) * 128 + m] = v.y;
            xT[(k4 * 4 + 2) * 128 + m] = v.z;
            xT[(k4 * 4 + 3) * 128 + m] = v.w;
        }
    } else {
#pragma unroll
        for (int it = 0; it < 128 * KK / 256; it++) {
            int idx = tid + it * 256;
            int m = idx % 128, k = idx / 128;
            xT[k * 128 + m] = (k < KREAL) ? A[(size_t)(m0g + m) * lda + k] : 0.f;
        }
    }
#pragma unroll
    for (int it = 0; it < KK * 16 / 256; it++) {
        int idx = tid + it * 256;
        int n4 = idx % 16, k = idx / 16;
        *(float4*)&ws[k * 64 + n4 * 4] =
            *(const float4*)&Wt[(size_t)k * NN2 + n0g + n4 * 4];
    }
    __syncthreads();

    const int ty = tid / 16, tx = tid % 16;
    const int m0 = ty * 8, n0 = tx * 4;

    unsigned long long acc[4][4];
#pragma unroll
    for (int j = 0; j < 4; j++)
#pragma unroll
        for (int p = 0; p < 4; p++) acc[j][p] = 0ull;

#pragma unroll 4
    for (int k = 0; k < KK; k++) {
        ulonglong2 xa = *(const ulonglong2*)&xT[k * 128 + m0];
        ulonglong2 xb = *(const ulonglong2*)&xT[k * 128 + m0 + 4];
        float4 wv = *(const float4*)&ws[k * 64 + n0];
        unsigned long long w0 = dup2(wv.x), w1 = dup2(wv.y),
                           w2 = dup2(wv.z), w3 = dup2(wv.w);
        fma2(acc[0][0], w0, xa.x); fma2(acc[0][1], w0, xa.y);
        fma2(acc[0][2], w0, xb.x); fma2(acc[0][3], w0, xb.y);
        fma2(acc[1][0], w1, xa.x); fma2(acc[1][1], w1, xa.y);
        fma2(acc[1][2], w1, xb.x); fma2(acc[1][3], w1, xb.y);
        fma2(acc[2][0], w2, xa.x); fma2(acc[2][1], w2, xa.y);
        fma2(acc[2][2], w2, xb.x); fma2(acc[2][3], w2, xb.y);
        fma2(acc[3][0], w3, xa.x); fma2(acc[3][1], w3, xa.y);
        fma2(acc[3][2], w3, xb.x); fma2(acc[3][3], w3, xb.y);
    }

    float bias[4];
#pragma unroll
    for (int j = 0; j < 4; j++) {
        int ng = n0g + n0 + j;
        bias[j] = (ng < GG) ? bf[ng] : bb[ng - GG];
    }
    float2 u[4][4];
#pragma unroll
    for (int j = 0; j < 4; j++)
#pragma unroll
        for (int p = 0; p < 4; p++) u[j][p] = unpk(acc[j][p]);

#pragma unroll
    for (int i = 0; i < 8; i++) {
        int p = i >> 1, h = i & 1;
        float4 o;
        o.x = (h ? u[0][p].y : u[0][p].x) + bias[0];
        o.y = (h ? u[1][p].y : u[1][p].x) + bias[1];
        o.z = (h ? u[2][p].y : u[2][p].x) + bias[2];
        o.w = (h ? u[3][p].y : u[3][p].x) + bias[3];
        size_t m = (size_t)(m0g + m0 + i);
        *(float4*)&gx[m * NN2 + n0g + n0] = o;
    }
}

// ---------------------------------------------------------------------------
// Recurrence v9: j-QUAD threads, RR=2 rows, 2 CTAs/SM.
//   192 threads = 6 warps. Thread = (j4 = tid%48 -> gate rows 4j4..4j4+3,
//   seg = tid/48 -> K-quarter of 16 c's). Weights j-pair packed:
//   wp01/wp23 (32 u64 = 64 regs). h stored dup'd: h_sm[k] = (h0,h0,h1,h1);
//   one 16B broadcast LDS feeds 4 FFMA2 (v4's crossbar ratio preserved).
//   grid = 256 CTAs -> 2 CTAs/SM: cross-CTA overlap hides barrier/gate/LDS
//   stalls while the per-SM FFMA2 floor is conserved.
// ---------------------------------------------------------------------------
#define RBD 192
#define RRC 2
__global__ void __launch_bounds__(RBD, 2) rec_kernel(
    const float* __restrict__ gx,   // [B*T][384], this dir at +dir*192
    const float* __restrict__ Whh_f, const float* __restrict__ bhh_f,
    const float* __restrict__ Whh_b, const float* __restrict__ bhh_b,
    float* __restrict__ out_seq,    // g_out0 or nullptr
    float* __restrict__ hT)         // g_hT or nullptr
{
    const int dir = blockIdx.y;
    const int b0  = blockIdx.x * RRC;
    const int tid = threadIdx.x;
    const int j4  = tid % 48;       // gate-row quad -> rows 4j4 .. 4j4+3
    const int seg = tid / 48;       // 0..3

    const float* Whh = dir ? Whh_b : Whh_f;
    const float* bhh = dir ? bhh_b : bhh_f;

    // j-pair packed weights: wp01[c]=(W[j0][cc],W[j1][cc]), wp23=(W[j2],W[j3])
    unsigned long long wp01[16], wp23[16];
#pragma unroll
    for (int c = 0; c < 16; c++) {
        const int cc = seg * 16 + c;
        wp01[c] = pack2(Whh[(j4 * 4 + 0) * HH + cc], Whh[(j4 * 4 + 1) * HH + cc]);
        wp23[c] = pack2(Whh[(j4 * 4 + 2) * HH + cc], Whh[(j4 * 4 + 3) * HH + cc]);
    }

    __shared__ __align__(16) float h_sm[HH * 4];      // [k]: (h0,h0,h1,h1)
    __shared__ __align__(16) float x_sm[2][RRC][GG];
    __shared__ __align__(16) float P_sm[4][RRC][GG];

    for (int e = tid; e < HH * 4; e += RBD) h_sm[e] = 0.f;

    // gate-math thread state (tid < 128): element (r,k)
    const int gr = tid >> 6, gk = tid & 63;
    float h_reg = 0.f, bhr = 0.f, bhz = 0.f, bhn = 0.f;
    if (tid < RRC * HH) {
        bhr = bhh[gk];
        bhz = bhh[64 + gk];
        bhn = bhh[128 + gk];
    }

    const int tstep = dir ? -1 : 1;
    int t = dir ? (TT - 1) : 0;

    // prefetch lanes: 2*192 = 384 gx floats/step, 96 threads x LDG.128
    const bool pf_lane = (tid < 96);
    const int pr = tid / 48, pg = (tid % 48) * 4;
    const size_t pbase = ((size_t)(b0 + pr) * TT) * NN2 + (size_t)dir * GG + pg;

    float4 pf_next = make_float4(0.f, 0.f, 0.f, 0.f);
    if (pf_lane) {
        *(float4*)&x_sm[0][pr][pg] = *(const float4*)&gx[pbase + (size_t)t * NN2];
        if (TT > 1)
            pf_next = *(const float4*)&gx[pbase + (size_t)(t + tstep) * NN2];
    }
    __syncthreads();

    for (int s = 0; s < TT; s++, t += tstep) {
        const int cur = s & 1;

        // issue LDG for step s+2 now (consumed at step s+1's store)
        float4 pf_next2 = make_float4(0.f, 0.f, 0.f, 0.f);
        if (pf_lane && s + 2 < TT)
            pf_next2 = *(const float4*)&gx[pbase + (size_t)(t + 2 * tstep) * NN2];

        // hidden GEMV: 4 gate rows (2 packed pairs) x 2 batch rows, quarter-K
        unsigned long long a01r0 = 0ull, a01r1 = 0ull;
        unsigned long long a23r0 = 0ull, a23r1 = 0ull;
#pragma unroll
        for (int c = 0; c < 16; c++) {
            ulonglong2 hq = *(const ulonglong2*)&h_sm[(seg * 16 + c) * 4];
            fma2(a01r0, wp01[c], hq.x);   // (h0,h0)
            fma2(a01r1, wp01[c], hq.y);   // (h1,h1)
            fma2(a23r0, wp23[c], hq.x);
            fma2(a23r1, wp23[c], hq.y);
        }
        {
            float2 u01r0 = unpk(a01r0), u23r0 = unpk(a23r0);
            float2 u01r1 = unpk(a01r1), u23r1 = unpk(a23r1);
            *(float4*)&P_sm[seg][0][j4 * 4] =
                make_float4(u01r0.x, u01r0.y, u23r0.x, u23r0.y);
            *(float4*)&P_sm[seg][1][j4 * 4] =
                make_float4(u01r1.x, u01r1.y, u23r1.x, u23r1.y);
        }

        // store gx for step s+1 (its LDG was issued one full step ago)
        if (pf_lane && s + 1 < TT) *(float4*)&x_sm[cur ^ 1][pr][pg] = pf_next;
        pf_next = pf_next2;
        __syncthreads();

        if (tid < RRC * HH) {
            float hr = P_sm[0][gr][gk]       + P_sm[1][gr][gk]
                     + P_sm[2][gr][gk]       + P_sm[3][gr][gk]       + bhr;
            float hz = P_sm[0][gr][64 + gk]  + P_sm[1][gr][64 + gk]
                     + P_sm[2][gr][64 + gk]  + P_sm[3][gr][64 + gk]  + bhz;
            float hn = P_sm[0][gr][128 + gk] + P_sm[1][gr][128 + gk]
                     + P_sm[2][gr][128 + gk] + P_sm[3][gr][128 + gk] + bhn;
            float rg = sigf(x_sm[cur][gr][gk]       + hr);
            float zg = sigf(x_sm[cur][gr][64 + gk]  + hz);
            float ng = tanh_f(x_sm[cur][gr][128 + gk] + rg * hn);
            h_reg = (1.f - zg) * ng + zg * h_reg;
            *(float2*)&h_sm[gk * 4 + gr * 2] = make_float2(h_reg, h_reg);
            if (out_seq)
                out_seq[((size_t)(b0 + gr) * TT + t) * 128 + dir * HH + gk] = h_reg;
        }
        __syncthreads();
    }

    if (hT && tid < RRC * HH)
        hT[(b0 + gr) * 128 + dir * HH + gk] = h_reg;
}

// ---------------------------------------------------------------------------
// Head: LayerNorm(128) -> Linear(128->64)+ReLU -> Linear(64->11)
// ---------------------------------------------------------------------------
__global__ void __launch_bounds__(128, 4) head_kernel(
    const float* __restrict__ ln_g, const float* __restrict__ ln_b,
    const float* __restrict__ W1, const float* __restrict__ b1,
    const float* __restrict__ W2, const float* __restrict__ b2,
    float* __restrict__ out)
{
    const int b = blockIdx.x;
    const int tid = threadIdx.x;
    const int lane = tid & 31, wid = tid >> 5;

    __shared__ float y_sm[128];
    __shared__ float h_sm[HH];
    __shared__ float r1[4], r2[4];
    __shared__ float stats[2];

    float e = g_hT[b * 128 + tid];
    float s1 = e, s2 = e * e;
#pragma unroll
    for (int o = 16; o; o >>= 1) {
        s1 += __shfl_down_sync(0xffffffffu, s1, o);
        s2 += __shfl_down_sync(0xffffffffu, s2, o);
    }
    if (lane == 0) { r1[wid] = s1; r2[wid] = s2; }
    __syncthreads();
    if (tid == 0) {
        float a = r1[0] + r1[1] + r1[2] + r1[3];
        float c = r2[0] + r2[1] + r2[2] + r2[3];
        float mu = a * (1.f / 128.f);
        float var = c * (1.f / 128.f) - mu * mu;
        stats[0] = mu;
        stats[1] = rsqrtf(var + 1e-5f);
    }
    __syncthreads();
    y_sm[tid] = (e - stats[0]) * stats[1] * ln_g[tid] + ln_b[tid];
    __syncthreads();

    if (tid < HH) {
        float acc = b1[tid];
#pragma unroll
        for (int kk = 0; kk < 128; kk++) acc += W1[tid * 128 + kk] * y_sm[kk];
        h_sm[tid] = fmaxf(acc, 0.f);
    }
    __syncthreads();
    if (tid < OUTD) {
        float acc = b2[tid];
#pragma unroll
        for (int kk = 0; kk < HH; kk++) acc += W2[tid * HH + kk] * h_sm[kk];
        out[b * OUTD + tid] = acc;
    }
}

// ---------------------------------------------------------------------------
extern "C" void kernel_launch(void* const* d_in, const int* in_sizes, int n_in,
                              void* d_out, int out_size) {
    (void)in_sizes; (void)n_in; (void)out_size;
    const float* x     = (const float*)d_in[0];
    const float* Wih00 = (const float*)d_in[1];
    const float* Whh00 = (const float*)d_in[2];
    const float* bih00 = (const float*)d_in[3];
    const float* bhh00 = (const float*)d_in[4];
    const float* Wih01 = (const float*)d_in[5];
    const float* Whh01 = (const float*)d_in[6];
    const float* bih01 = (const float*)d_in[7];
    const float* bhh01 = (const float*)d_in[8];
    const float* Wih10 = (const float*)d_in[9];
    const float* Whh10 = (const float*)d_in[10];
    const float* bih10 = (const float*)d_in[11];
    const float* bhh10 = (const float*)d_in[12];
    const float* Wih11 = (const float*)d_in[13];
    const float* Whh11 = (const float*)d_in[14];
    const float* bih11 = (const float*)d_in[15];
    const float* bhh11 = (const float*)d_in[16];
    const float* ln_g  = (const float*)d_in[17];
    const float* ln_b  = (const float*)d_in[18];
    const float* W1    = (const float*)d_in[19];
    const float* b1    = (const float*)d_in[20];
    const float* W2    = (const float*)d_in[21];
    const float* b2    = (const float*)d_in[22];
    float* out = (float*)d_out;

    float* gx0  = nullptr; cudaGetSymbolAddress((void**)&gx0,  g_gx0);
    float* gx1  = nullptr; cudaGetSymbolAddress((void**)&gx1,  g_gx1);
    float* out0 = nullptr; cudaGetSymbolAddress((void**)&out0, g_out0);
    float* hT   = nullptr; cudaGetSymbolAddress((void**)&hT,   g_hT);
    float* Wt0  = nullptr; cudaGetSymbolAddress((void**)&Wt0,  g_Wt0);
    float* Wt1  = nullptr; cudaGetSymbolAddress((void**)&Wt1,  g_Wt1);

    const int smem32  = (32 * 128 + 32 * 64) * 4;
    const int smem128 = (128 * 128 + 128 * 64) * 4;
    cudaFuncSetAttribute(gemm_gx_kernel<32, 29>,
                         cudaFuncAttributeMaxDynamicSharedMemorySize, smem32);
    cudaFuncSetAttribute(gemm_gx_kernel<128, 128>,
                         cudaFuncAttributeMaxDynamicSharedMemorySize, smem128);

    // one-time weight transposes (tiny)
    transpose_w_kernel<<<(32 * NN2 + 255) / 256, 256>>>(Wih00, Wih01, Wt0, 32, INP);
    transpose_w_kernel<<<(128 * NN2 + 255) / 256, 256>>>(Wih10, Wih11, Wt1, 128, 128);

    dim3 ggrid(6, MT / 128);      // n-tiles fastest -> A tile read ~once from DRAM
    dim3 rgrid(BB / RRC, 2);      // 256 CTAs -> 2 CTAs/SM

    gemm_gx_kernel<32, 29><<<ggrid, 256, smem32>>>(x, INP, Wt0, bih00, bih01, gx0);
    rec_kernel<<<rgrid, RBD>>>(gx0, Whh00, bhh00, Whh01, bhh01, out0, nullptr);
    gemm_gx_kernel<128, 128><<<ggrid, 256, smem128>>>(out0, 128, Wt1, bih10, bih11, gx1);
    rec_kernel<<<rgrid, RBD>>>(gx1, Whh10, bhh10, Whh11, bhh11, nullptr, hT);
    head_kernel<<<BB, 128>>>(ln_g, ln_b, W1, b1, W2, b2, out);
}